// round 6
// baseline (speedup 1.0000x reference)
#include <cuda_runtime.h>

// GAE backward scan, round 6: single-node graph via monotonic epoch flags
// (no reset kernel), acquire-load polling (no RMW spin), DEPTH=6 lookback.
// adv[t] = delta[t] + GL*adv[t+1],  delta[t] = r[t] + GAMMA*v[t+1] - v[t]
// 32 time-chunks x 128 column-groups (256 cols each, float2/thread), grid 4096.
// Flags are never reset: publisher of replay E writes E+1; consumers wait
// for >= E+1. Flags/ticket are monotone across graph replays; per-call output
// is identical (work mapping uses ticket & 4095 only).

#define B_COLS 32768
#define TM1 1023            // output rows t = 0 .. 1022
#define GAMMA 0.99f
#define GL (0.99f * 0.95f)
#define NCHUNK 32
#define RMAX 32             // rows per chunk (last chunk: 31 valid)
#define GBLK 128            // column groups of 256 columns (B_COLS / 256)
#define NBLK (NCHUNK * GBLK)   // 4096
#define DEPTH 6             // gl^(32*6) ~ 7.7e-6 << 1e-3 tolerance

__device__ float g_scratch[NCHUNK * B_COLS];  // C_k per (chunk, column)
__device__ int   g_flags[NCHUNK * GBLK];      // epoch-stamped publish flags (zero-init)
__device__ unsigned int g_ticket;             // monotonic across replays (zero-init)

__global__ __launch_bounds__(128) void gae_chunk_kernel(
    const float* __restrict__ rewards,
    const float* __restrict__ values,
    float* __restrict__ out)
{
    __shared__ unsigned int s_ticket;
    if (threadIdx.x == 0) s_ticket = atomicAdd(&g_ticket, 1u);
    __syncthreads();
    const unsigned int ticket = s_ticket;
    const int epoch = (int)(ticket / NBLK);       // replay index
    const int want  = epoch + 1;
    const unsigned int local_tk = ticket & (NBLK - 1);
    const int k  = (int)(local_tk >> 7);          // chunk 0..31 (0 = highest t)
    const int gx = (int)(local_tk & (GBLK - 1));  // column group
    const int c2 = gx * 128 + threadIdx.x;        // float2 column index
    const int ROW2 = B_COLS / 2;                  // row stride in float2
    const int t_hi = (TM1 - 1) - RMAX * k;        // 1022 - 32k

    const float2* r = (const float2*)rewards + c2;
    const float2* v = (const float2*)values + c2;
    float2* o = (float2*)out + c2;

    // ---- local backward scan (carry-in = 0), 32 rows, batched LDG.64 ----
    float2 local[RMAX];
    float ax = 0.0f, ay = 0.0f;
    float2 vn = __ldcs(v + (t_hi + 1) * ROW2);

    if (k < NCHUNK - 1) {
        #pragma unroll
        for (int g0 = 0; g0 < RMAX; g0 += 8) {
            float2 rt[8], vt[8];
            #pragma unroll
            for (int i = 0; i < 8; ++i) {
                const int t = t_hi - (g0 + i);
                rt[i] = __ldcs(r + t * ROW2);
                vt[i] = __ldcs(v + t * ROW2);
            }
            #pragma unroll
            for (int i = 0; i < 8; ++i) {
                const float dx = fmaf(GAMMA, vn.x, rt[i].x) - vt[i].x;
                const float dy = fmaf(GAMMA, vn.y, rt[i].y) - vt[i].y;
                ax = fmaf(GL, ax, dx);
                ay = fmaf(GL, ay, dy);
                local[g0 + i] = make_float2(ax, ay);
                vn = vt[i];
            }
        }
        // publish chunk-sum C_k with epoch stamp
        *(float2*)&g_scratch[k * B_COLS + 2 * c2] = local[RMAX - 1];
        __threadfence();
        __syncthreads();
        if (threadIdx.x == 0)
            atomicExch(&g_flags[k * GBLK + gx], want);
    } else {
        // Last chunk (k=31): t = 30..0; row 31 invalid. No consumers -> no publish.
        #pragma unroll
        for (int g0 = 0; g0 < RMAX; g0 += 8) {
            float2 rt[8], vt[8];
            #pragma unroll
            for (int i = 0; i < 8; ++i) {
                const int t = t_hi - (g0 + i);
                if (t >= 0) {
                    rt[i] = __ldcs(r + t * ROW2);
                    vt[i] = __ldcs(v + t * ROW2);
                } else {
                    rt[i] = make_float2(0.0f, 0.0f);
                    vt[i] = make_float2(0.0f, 0.0f);
                }
            }
            #pragma unroll
            for (int i = 0; i < 8; ++i) {
                const float dx = fmaf(GAMMA, vn.x, rt[i].x) - vt[i].x;
                const float dy = fmaf(GAMMA, vn.y, rt[i].y) - vt[i].y;
                ax = fmaf(GL, ax, dx);
                ay = fmaf(GL, ay, dy);
                local[g0 + i] = make_float2(ax, ay);
                vn = vt[i];
            }
        }
    }

    // ---- truncated lookback: A = sum_{j=k-1 .. k-d} C_j * gl^(32*(k-1-j)) ----
    float Ax = 0.0f, Ay = 0.0f;
    if (k > 0) {
        const int d = (k < DEPTH) ? k : DEPTH;
        if (threadIdx.x < d) {  // thread i waits on predecessor (k-1-i)
            const int* fp = &g_flags[(k - 1 - (int)threadIdx.x) * GBLK + gx];
            int f;
            do {
                asm volatile("ld.acquire.gpu.global.b32 %0, [%1];"
                             : "=r"(f) : "l"(fp) : "memory");
            } while (f < want);
        }
        __syncthreads();

        // gl^32 via 5 squarings
        const float g2 = GL * GL, g4 = g2 * g2, g8 = g4 * g4;
        const float g16 = g8 * g8, gl32 = g16 * g16;

        float w = 1.0f;
        for (int j = k - 1; j >= k - d; --j) {
            const float2 Cj = *(const float2*)&g_scratch[j * B_COLS + 2 * c2];
            Ax = fmaf(Cj.x, w, Ax);
            Ay = fmaf(Cj.y, w, Ay);
            w *= gl32;
        }
    }

    // ---- fixup + store: adv[t_hi - i] = local[i] + A * gl^(i+1) ----
    if (k < NCHUNK - 1) {
        #pragma unroll
        for (int i = 0; i < RMAX; ++i) {
            Ax *= GL;
            Ay *= GL;
            __stcs(o + (t_hi - i) * ROW2,
                   make_float2(local[i].x + Ax, local[i].y + Ay));
        }
    } else {
        #pragma unroll
        for (int i = 0; i < RMAX; ++i) {
            const int t = t_hi - i;
            Ax *= GL;
            Ay *= GL;
            if (t >= 0)
                __stcs(o + t * ROW2,
                       make_float2(local[i].x + Ax, local[i].y + Ay));
        }
    }
}

extern "C" void kernel_launch(void* const* d_in, const int* in_sizes, int n_in,
                              void* d_out, int out_size) {
    const float* rewards = (const float*)d_in[0];
    const float* values  = (const float*)d_in[1];
    float* out = (float*)d_out;

    gae_chunk_kernel<<<NBLK, 128>>>(rewards, values, out);
}